// round 5
// baseline (speedup 1.0000x reference)
#include <cuda_runtime.h>
#include <math_constants.h>
#include <stdint.h>

#define BROWS 2048
#define CCOLS 9605
#define TPB   256
#define TOPK  10
#define LN2F  0.69314718055994531f

// spline table: f_neg(x) over [TXMIN, TXMAX], 512 cubic-Hermite intervals
#define TN     512
#define TXMIN  -8.0f
#define TH     0.03125f      // 16/512
#define TINVH  32.0f
#define TOFF   256.0f        // -TXMIN*TINVH

__device__ float g_partial[BROWS];
__device__ int   g_count = 0;

// exact positive-path (y=1): log2(p) * (1-p)
__device__ __forceinline__ float posExact2(float xv) {
    float e = __expf(-xv);
    float p = __fdividef(1.0f, 1.0f + e);
    return __log2f(p) * (1.0f - p);
}

// spline negative-path (y=0): log2(min(1.05-p,1)) * (1-min(1.05-p,1))^4, log2 domain
__device__ __forceinline__ float negSpline(float xv, const float4* __restrict__ tbl) {
    float s = fmaf(xv, TINVH, TOFF);
    s = fminf(fmaxf(s, 0.0f), 511.999f);
    float kf = floorf(s);
    float t  = s - kf;
    float4 c = tbl[(int)kf];
    return fmaf(fmaf(fmaf(c.w, t, c.z), t, c.y), t, c.x);
}

__device__ __forceinline__ float termEval(float xv, float yv, const float4* __restrict__ tbl) {
    return (yv > 0.5f) ? posExact2(xv) : negSpline(xv, tbl);
}

__global__ __launch_bounds__(TPB, 8)
void asl_fused_kernel(const float* __restrict__ x,
                      const float* __restrict__ y,
                      const int*   __restrict__ compost,
                      const int*   __restrict__ recycle,
                      const int*   __restrict__ donate,
                      const int*   __restrict__ wl_map,
                      float*       __restrict__ out)
{
    __shared__ float4 stbl[TN];          // 8 KB spline coeffs
    __shared__ float  sf[TN + 1];
    __shared__ float  sd[TN + 1];
    __shared__ float  sval[TPB];
    __shared__ int    sidx[TPB];
    __shared__ float  swsum[TPB / 32];
    __shared__ int    sflags;
    __shared__ int    s_top_idx[TOPK];
    __shared__ float  s_top_val[TOPK];
    __shared__ float  s_g[TOPK];
    __shared__ float  s_corr[TOPK];
    __shared__ int    swin_idx;
    __shared__ int    s_last;

    const int row = blockIdx.x;
    const int tid = threadIdx.x;
    const int wid = tid >> 5;
    const int lid = tid & 31;
    const float* __restrict__ xr = x + (size_t)row * CCOLS;
    const float* __restrict__ yr = y + (size_t)row * CCOLS;

    const int c0 = (4 - (row & 3)) & 3;
    const int nv = (CCOLS - c0) >> 2;
    const int ct = c0 + 4 * nv;

    if (tid == 0) sflags = 0;

    // ---- build spline knots (identical in every block -> deterministic) ----
    for (int k = tid; k < TN + 1; k += TPB) {
        float xk = TXMIN + TH * (float)k;
        float e  = __expf(xk);
        float u  = __fdividef(1.0f, 1.0f + e);       // sigma(-x)
        float q  = fminf(u + 0.05f, 1.0f);
        float g  = fmaxf(0.95f - u, 0.0f);
        float lg = __log2f(q);
        float g2 = g * g, g3 = g2 * g, g4 = g2 * g2;
        float fk = lg * g4;
        float dk = (g4 * __fdividef(1.0f, q * LN2F) - 4.0f * g3 * lg)
                   * (-u * (1.0f - u));
        sf[k] = fk;
        sd[k] = dk * TH;
    }
    __syncthreads();
    for (int k = tid; k < TN; k += TPB) {
        float f0 = sf[k], f1 = sf[k + 1];
        float m0 = sd[k], m1 = sd[k + 1];
        stbl[k] = make_float4(f0, m0,
                              3.0f * (f1 - f0) - 2.0f * m0 - m1,
                              2.0f * (f0 - f1) + m0 + m1);
    }

    // per-row whitelist-group presence (raw index lists, overlaps matter)
    if (tid < 170) {
        int idx, bit;
        if (tid < 30)       { idx = compost[tid];        bit = 1; }
        else if (tid < 100) { idx = recycle[tid - 30];   bit = 2; }
        else                { idx = donate[tid - 100];   bit = 4; }
        if (yr[idx] > 0.0f) atomicOr(&sflags, bit);
    }
    __syncthreads();

    // ---- streaming pass: spline terms + per-thread running top-1 ----
    float lsum = 0.0f;
    float bv = -CUDART_INF_F;
    int   bi = 0;

    if (tid < c0) {
        float xv = xr[tid], yv = yr[tid];
        lsum += termEval(xv, yv, stbl);
        if (xv > bv) { bv = xv; bi = tid; }
    }

    const float4* __restrict__ x4 = (const float4*)(xr + c0);
    const float4* __restrict__ y4 = (const float4*)(yr + c0);
    for (int k = tid; k < nv; k += TPB) {
        float4 xa = x4[k];
        float4 ya = y4[k];
        int c = c0 + 4 * k;

        float t0 = negSpline(xa.x, stbl);
        float t1 = negSpline(xa.y, stbl);
        float t2 = negSpline(xa.z, stbl);
        float t3 = negSpline(xa.w, stbl);

        // rare positive fixup: warp-level branch (skipped for ~72% of groups)
        int pos = (ya.x > 0.5f) | ((ya.y > 0.5f) << 1) |
                  ((ya.z > 0.5f) << 2) | ((ya.w > 0.5f) << 3);
        unsigned am = __activemask();
        if (__any_sync(am, pos)) {
            if (pos & 1) t0 = posExact2(xa.x);
            if (pos & 2) t1 = posExact2(xa.y);
            if (pos & 4) t2 = posExact2(xa.z);
            if (pos & 8) t3 = posExact2(xa.w);
        }
        lsum += (t0 + t1) + (t2 + t3);

        if (xa.x > bv) { bv = xa.x; bi = c;     }
        if (xa.y > bv) { bv = xa.y; bi = c + 1; }
        if (xa.z > bv) { bv = xa.z; bi = c + 2; }
        if (xa.w > bv) { bv = xa.w; bi = c + 3; }
    }

    if (tid < CCOLS - ct) {
        int c = ct + tid;
        float xv = xr[c], yv = yr[c];
        lsum += termEval(xv, yv, stbl);
        if (xv > bv) { bv = xv; bi = c; }
    }

    sval[tid] = bv;
    sidx[tid] = bi;

    #pragma unroll
    for (int off = 16; off; off >>= 1)
        lsum += __shfl_down_sync(0xffffffffu, lsum, off);
    if (lid == 0) swsum[wid] = lsum;
    __syncthreads();

    // ---- top-10 tournament with warp-cooperative L2 rescan on pop ----
    for (int r = 0; r < TOPK; r++) {
        if (tid < 32) {
            float v = sval[tid];
            int   i = sidx[tid];
            #pragma unroll
            for (int w = 1; w < TPB / 32; w++) {
                float ov = sval[tid + 32 * w];
                int   oi = sidx[tid + 32 * w];
                if (ov > v || (ov == v && oi < i)) { v = ov; i = oi; }
            }
            #pragma unroll
            for (int off = 16; off; off >>= 1) {
                float ov = __shfl_down_sync(0xffffffffu, v, off);
                int   oi = __shfl_down_sync(0xffffffffu, i, off);
                if (ov > v || (ov == v && oi < i)) { v = ov; i = oi; }
            }
            if (tid == 0) {
                swin_idx     = i;
                s_top_idx[r] = i;
                s_top_val[r] = v;
            }
        }
        __syncthreads();

        if (r < TOPK - 1) {
            int wc = swin_idx;
            int owner = (wc < c0) ? wc
                       : (wc >= ct ? wc - ct
                                   : (((wc - c0) >> 2) & (TPB - 1)));
            if (wid == (owner >> 5)) {
                float rv = -CUDART_INF_F;
                int   ri = 0;
                int k2 = owner + TPB * lid;
                if (k2 < nv) {
                    float4 xa = x4[k2];
                    int c = c0 + 4 * k2;
                    float e4[4] = {xa.x, xa.y, xa.z, xa.w};
                    #pragma unroll
                    for (int e = 0; e < 4; e++) {
                        int cc = c + e;
                        bool cons = false;
                        for (int r2 = 0; r2 <= r; r2++)
                            cons |= (s_top_idx[r2] == cc);
                        float v = e4[e];
                        if (!cons && (v > rv || (v == rv && cc < ri)))
                            { rv = v; ri = cc; }
                    }
                }
                if (lid == 31) {
                    if (owner < c0) {
                        int cc = owner;
                        bool cons = false;
                        for (int r2 = 0; r2 <= r; r2++)
                            cons |= (s_top_idx[r2] == cc);
                        float v = xr[cc];
                        if (!cons && (v > rv || (v == rv && cc < ri)))
                            { rv = v; ri = cc; }
                    }
                    int cc = ct + owner;
                    if (cc < CCOLS) {
                        bool cons = false;
                        for (int r2 = 0; r2 <= r; r2++)
                            cons |= (s_top_idx[r2] == cc);
                        float v = xr[cc];
                        if (!cons && (v > rv || (v == rv && cc < ri)))
                            { rv = v; ri = cc; }
                    }
                }
                #pragma unroll
                for (int off = 16; off; off >>= 1) {
                    float ov = __shfl_down_sync(0xffffffffu, rv, off);
                    int   oi = __shfl_down_sync(0xffffffffu, ri, off);
                    if (ov > rv || (ov == rv && oi < ri)) { rv = ov; ri = oi; }
                }
                if (lid == 0) { sval[owner] = rv; sidx[owner] = ri; }
            }
        }
        __syncthreads();
    }

    // ---- sequential rank logic (exact scan semantics) ----
    if (tid == 0) {
        int flags = sflags;
        bool h1 = (flags & 1) != 0, h2 = (flags & 2) != 0, h3 = (flags & 4) != 0;
        bool gt4 = !(h1 | h2 | h3);
        bool found = false;
        float fr[TOPK];
        #pragma unroll
        for (int r = 0; r < TOPK; r++) {
            int j  = s_top_idx[r];
            int wl = wl_map[j];
            bool in_map = (wl > 0);
            bool in_gt  = (wl == 1 && h1) || (wl == 2 && h2) ||
                          (wl == 3 && h3) || (wl == 4 && gt4);
            float f = (in_map && gt4) ? 0.5f : 1.0f;
            if (in_map && !in_gt && !found) f *= 2.0f;
            fr[r] = f;
            found = found || (in_map && in_gt);
        }
        float extra = found ? 1.0f : 2.0f;
        #pragma unroll
        for (int r = 0; r < TOPK; r++) s_g[r] = fr[r] * extra - 1.0f;
    }
    __syncthreads();

    // corrections use the SAME hybrid evaluator as the stream (consistency)
    if (tid < TOPK) {
        int j = s_top_idx[tid];
        s_corr[tid] = termEval(s_top_val[tid], yr[j], stbl) * s_g[tid];
    }
    __syncthreads();

    if (tid == 0) {
        float s = 0.0f;
        #pragma unroll
        for (int w = 0; w < TPB / 32; w++) s += swsum[w];
        #pragma unroll
        for (int r = 0; r < TOPK; r++) s += s_corr[r];
        g_partial[row] = s;
    }

    // ---- deterministic last-block final reduction ----
    __threadfence();
    if (tid == 0) {
        int t = atomicAdd(&g_count, 1);
        s_last = (t == gridDim.x - 1) ? 1 : 0;
    }
    __syncthreads();
    if (s_last) {
        float v = 0.0f;
        #pragma unroll
        for (int i = 0; i < BROWS / TPB; i++)
            v += __ldcg(&g_partial[tid + i * TPB]);
        sval[tid] = v;
        __syncthreads();
        #pragma unroll
        for (int st = TPB / 2; st > 0; st >>= 1) {
            if (tid < st) sval[tid] += sval[tid + st];
            __syncthreads();
        }
        if (tid == 0) {
            out[0] = -LN2F * sval[0];   // log2 -> ln, negate
            g_count = 0;                // reset for graph replay
        }
    }
}

extern "C" void kernel_launch(void* const* d_in, const int* in_sizes, int n_in,
                              void* d_out, int out_size)
{
    const float* x       = (const float*)d_in[0];
    const float* y       = (const float*)d_in[1];
    const int*   compost = (const int*)d_in[2];
    const int*   recycle = (const int*)d_in[3];
    const int*   donate  = (const int*)d_in[4];
    const int*   wl_map  = (const int*)d_in[5];
    float* out = (float*)d_out;

    asl_fused_kernel<<<BROWS, TPB>>>(x, y, compost, recycle, donate, wl_map, out);
}